// round 3
// baseline (speedup 1.0000x reference)
#include <cuda_runtime.h>
#include <cuda_bf16.h>
#include <math_constants.h>

// Problem constants
#define BATCH 4
#define T_LEN 4096
#define EMBD 32
#define HEAD 32
#define BT (BATCH * T_LEN)

// Flash tiling
#define BR 128          // queries per CTA (== threads per CTA)
#define BC 128          // key tile held in smem
#define NSPLIT 4        // key-dimension splits for occupancy
#define SPLIT_LEN (T_LEN / NSPLIT)

// scale * log2(e): scores kept in log2 domain so softmax exp is one MUFU.EX2
#define SCALE2 0.25505654309411853f   // (1/sqrt(32)) * log2(e)

// -------- device scratch (static globals; no allocation) --------
__device__ float g_q[BT * HEAD];
__device__ float g_k[BT * HEAD];
__device__ float g_v[BT * HEAD];
__device__ float g_m[NSPLIT * BT];
__device__ float g_l[NSPLIT * BT];
__device__ float g_acc[NSPLIT * BT * HEAD];

__device__ __forceinline__ float exp2_approx(float x) {
    float y;
    asm("ex2.approx.ftz.f32 %0, %1;" : "=f"(y) : "f"(x));
    return y;
}

// ---------------- Kernel 1: QKV projection ----------------
// block = 256 threads = 8 rows x 32 head-dims; grid = BT/8
__global__ void proj_kernel(const float* __restrict__ x,
                            const float* __restrict__ Wq,
                            const float* __restrict__ Wk,
                            const float* __restrict__ Wv) {
    __shared__ float sWq[EMBD * HEAD];  // stored transposed: [d][h]
    __shared__ float sWk[EMBD * HEAD];
    __shared__ float sWv[EMBD * HEAD];
    __shared__ float sx[8][EMBD];

    int tid = threadIdx.x;
    // Load W (row-major [h][d]) transposed into smem as [d][h] for conflict-free reads
    for (int i = tid; i < EMBD * HEAD; i += 256) {
        int h = i / EMBD, d = i % EMBD;
        sWq[d * HEAD + h] = Wq[i];
        sWk[d * HEAD + h] = Wk[i];
        sWv[d * HEAD + h] = Wv[i];
    }
    int row0 = blockIdx.x * 8;
    int r = tid >> 5, h = tid & 31;
    sx[r][h] = x[(row0 + r) * EMBD + h];
    __syncthreads();

    float aq = 0.f, ak = 0.f, av = 0.f;
#pragma unroll
    for (int d = 0; d < EMBD; ++d) {
        float xv = sx[r][d];
        aq = fmaf(xv, sWq[d * HEAD + h], aq);
        ak = fmaf(xv, sWk[d * HEAD + h], ak);
        av = fmaf(xv, sWv[d * HEAD + h], av);
    }
    int row = row0 + r;
    g_q[row * HEAD + h] = aq;
    g_k[row * HEAD + h] = ak;
    g_v[row * HEAD + h] = av;
}

// ---------------- Kernel 2: flash attention partial (split-K) ----------------
// grid = (T/BR, NSPLIT, BATCH), block = BR threads, one thread per query row.
__global__ __launch_bounds__(BR) void flash_kernel() {
    __shared__ float Ks[BC * HEAD];
    __shared__ float Vs[BC * HEAD];

    int qtile = blockIdx.x, split = blockIdx.y, b = blockIdx.z;
    int tid = threadIdx.x;
    int q_idx = qtile * BR + tid;

    const float* kb = g_k + b * T_LEN * HEAD;
    const float* vb = g_v + b * T_LEN * HEAD;

    // q row in registers
    float q[HEAD];
    {
        const float4* qg = reinterpret_cast<const float4*>(g_q + (b * T_LEN + q_idx) * HEAD);
        float4* q4 = reinterpret_cast<float4*>(q);
#pragma unroll
        for (int i = 0; i < 8; ++i) q4[i] = qg[i];
    }

    float m = -CUDART_INF_F;
    float l = 0.f;
    float acc[HEAD];
#pragma unroll
    for (int h = 0; h < HEAD; ++h) acc[h] = 0.f;

    int kv_begin = split * SPLIT_LEN;
    int kv_end = min((split + 1) * SPLIT_LEN, qtile * BR + BR);  // causal clip for tile

    for (int t0 = kv_begin; t0 < kv_end; t0 += BC) {
        // cooperative tile load (always full BC rows; t0+BC <= T always)
        {
            const float4* kg = reinterpret_cast<const float4*>(kb + t0 * HEAD);
            const float4* vg = reinterpret_cast<const float4*>(vb + t0 * HEAD);
            float4* ks4 = reinterpret_cast<float4*>(Ks);
            float4* vs4 = reinterpret_cast<float4*>(Vs);
#pragma unroll
            for (int i = 0; i < 8; ++i) {
                int idx = i * BR + tid;
                ks4[idx] = kg[idx];
                vs4[idx] = vg[idx];
            }
        }
        __syncthreads();

        int jmax = min(BC, kv_end - t0);
        int jlim = min(jmax, q_idx - t0 + 1);  // per-thread causal bound

        for (int jj = 0; jj < jlim; ++jj) {
            const float4* kj = reinterpret_cast<const float4*>(Ks + jj * HEAD);
            float s0 = 0.f, s1 = 0.f, s2 = 0.f, s3 = 0.f;
#pragma unroll
            for (int i = 0; i < 8; ++i) {
                float4 kv = kj[i];
                s0 = fmaf(q[4 * i + 0], kv.x, s0);
                s1 = fmaf(q[4 * i + 1], kv.y, s1);
                s2 = fmaf(q[4 * i + 2], kv.z, s2);
                s3 = fmaf(q[4 * i + 3], kv.w, s3);
            }
            float s = ((s0 + s1) + (s2 + s3)) * SCALE2;
            // Faithful to reference: tril entries that are exactly 0 get masked too.
            if (s != 0.0f) {
                float p;
                if (s > m) {
                    float c = exp2_approx(m - s);  // m=-inf first time -> c=0
                    m = s;
                    l *= c;
#pragma unroll
                    for (int h = 0; h < HEAD; ++h) acc[h] *= c;
                    p = 1.0f;
                } else {
                    p = exp2_approx(s - m);
                }
                l += p;
                const float4* vj = reinterpret_cast<const float4*>(Vs + jj * HEAD);
#pragma unroll
                for (int i = 0; i < 8; ++i) {
                    float4 vv = vj[i];
                    acc[4 * i + 0] = fmaf(p, vv.x, acc[4 * i + 0]);
                    acc[4 * i + 1] = fmaf(p, vv.y, acc[4 * i + 1]);
                    acc[4 * i + 2] = fmaf(p, vv.z, acc[4 * i + 2]);
                    acc[4 * i + 3] = fmaf(p, vv.w, acc[4 * i + 3]);
                }
            }
        }
        __syncthreads();
    }

    // write partials: layout [split][b*T + q]
    int base = split * BT + (b * T_LEN + q_idx);
    g_m[base] = m;
    g_l[base] = l;
    float4* ag = reinterpret_cast<float4*>(g_acc + base * HEAD);
    const float4* a4 = reinterpret_cast<const float4*>(acc);
#pragma unroll
    for (int i = 0; i < 8; ++i) ag[i] = a4[i];
}

// ---------------- Kernel 3: split-K combine ----------------
__global__ void combine_kernel(float* __restrict__ out) {
    int bt = blockIdx.x * blockDim.x + threadIdx.x;
    if (bt >= BT) return;

    float ms[NSPLIT], ls[NSPLIT];
    float M = -CUDART_INF_F;
#pragma unroll
    for (int s = 0; s < NSPLIT; ++s) {
        ms[s] = g_m[s * BT + bt];
        ls[s] = g_l[s * BT + bt];
        M = fmaxf(M, ms[s]);
    }
    float w[NSPLIT];
    float L = 0.f;
#pragma unroll
    for (int s = 0; s < NSPLIT; ++s) {
        w[s] = (ms[s] == -CUDART_INF_F) ? 0.f : exp2_approx(ms[s] - M);
        L = fmaf(ls[s], w[s], L);
    }
    float inv = 1.0f / L;

    float4* og = reinterpret_cast<float4*>(out + bt * HEAD);
#pragma unroll
    for (int i = 0; i < 8; ++i) {
        float4 o = make_float4(0.f, 0.f, 0.f, 0.f);
#pragma unroll
        for (int s = 0; s < NSPLIT; ++s) {
            const float4 a = reinterpret_cast<const float4*>(
                g_acc + (s * BT + bt) * HEAD)[i];
            o.x = fmaf(a.x, w[s], o.x);
            o.y = fmaf(a.y, w[s], o.y);
            o.z = fmaf(a.z, w[s], o.z);
            o.w = fmaf(a.w, w[s], o.w);
        }
        o.x *= inv; o.y *= inv; o.z *= inv; o.w *= inv;
        og[i] = o;
    }
}

extern "C" void kernel_launch(void* const* d_in, const int* in_sizes, int n_in,
                              void* d_out, int out_size) {
    const float* x  = (const float*)d_in[0];
    const float* Wq = (const float*)d_in[1];
    const float* Wk = (const float*)d_in[2];
    const float* Wv = (const float*)d_in[3];
    float* out = (float*)d_out;

    proj_kernel<<<BT / 8, 256>>>(x, Wq, Wk, Wv);
    flash_kernel<<<dim3(T_LEN / BR, NSPLIT, BATCH), BR>>>();
    combine_kernel<<<(BT + 127) / 128, 128>>>(out);
}

// round 6
// speedup vs baseline: 2.6134x; 2.6134x over previous
#include <cuda_runtime.h>
#include <cuda_bf16.h>
#include <math_constants.h>

// Problem constants
#define BATCH 4
#define T_LEN 4096
#define EMBD 32
#define HEAD 32
#define BT (BATCH * T_LEN)

// Flash tiling
#define BR 128          // queries per CTA (== threads per CTA)
#define BC 128          // key tile held in smem
#define NSPLIT 8        // key-dimension splits for occupancy / load balance
#define SPLIT_LEN (T_LEN / NSPLIT)

// scale * log2(e): scores kept in log2 domain so softmax exp is one MUFU.EX2
#define SCALE2 0.25505654309411853f   // (1/sqrt(32)) * log2(e)

typedef unsigned long long u64;

// -------- device scratch (static globals; no allocation) --------
__device__ float g_q[BT * HEAD];
__device__ float g_k[BT * HEAD];
__device__ float g_v[BT * HEAD];
__device__ float g_m[NSPLIT * BT];
__device__ float g_l[NSPLIT * BT];
__device__ float g_acc[NSPLIT * BT * HEAD];   // zero-initialized; empty splits never write

__device__ __forceinline__ float exp2_approx(float x) {
    float y;
    asm("ex2.approx.ftz.f32 %0, %1;" : "=f"(y) : "f"(x));
    return y;
}
// ---- packed fp32x2 ops (Blackwell FFMA2 path; ptxas won't emit these from C++) ----
__device__ __forceinline__ u64 pack2(float lo, float hi) {
    u64 r; asm("mov.b64 %0, {%1, %2};" : "=l"(r) : "f"(lo), "f"(hi)); return r;
}
__device__ __forceinline__ void unpack2(u64 v, float& lo, float& hi) {
    asm("mov.b64 {%0, %1}, %2;" : "=f"(lo), "=f"(hi) : "l"(v));
}
__device__ __forceinline__ u64 ffma2(u64 a, u64 b, u64 c) {
    u64 d; asm("fma.rn.f32x2 %0, %1, %2, %3;" : "=l"(d) : "l"(a), "l"(b), "l"(c)); return d;
}
__device__ __forceinline__ u64 fmul2(u64 a, u64 b) {
    u64 d; asm("mul.rn.f32x2 %0, %1, %2;" : "=l"(d) : "l"(a), "l"(b)); return d;
}
__device__ __forceinline__ u64 fadd2(u64 a, u64 b) {
    u64 d; asm("add.rn.f32x2 %0, %1, %2;" : "=l"(d) : "l"(a), "l"(b)); return d;
}

// ---------------- Kernel 1: QKV projection ----------------
// block = 256 threads = 8 rows x 32 head-dims; grid = BT/8
// smem W stored transposed [d][h] with stride 33 -> conflict-free stores AND loads.
#define WPITCH (HEAD + 1)
__global__ void proj_kernel(const float* __restrict__ x,
                            const float* __restrict__ Wq,
                            const float* __restrict__ Wk,
                            const float* __restrict__ Wv) {
    __shared__ float sWq[EMBD * WPITCH];
    __shared__ float sWk[EMBD * WPITCH];
    __shared__ float sWv[EMBD * WPITCH];
    __shared__ float sx[8][EMBD];

    int tid = threadIdx.x;
    for (int i = tid; i < EMBD * HEAD; i += 256) {
        int h = i / EMBD, d = i % EMBD;          // consecutive lanes: same h, d+1 -> stride 33 -> no conflict
        sWq[d * WPITCH + h] = Wq[i];
        sWk[d * WPITCH + h] = Wk[i];
        sWv[d * WPITCH + h] = Wv[i];
    }
    int row0 = blockIdx.x * 8;
    int r = tid >> 5, h = tid & 31;
    sx[r][h] = x[(row0 + r) * EMBD + h];
    __syncthreads();

    float aq = 0.f, ak = 0.f, av = 0.f;
#pragma unroll
    for (int d = 0; d < EMBD; ++d) {
        float xv = sx[r][d];
        aq = fmaf(xv, sWq[d * WPITCH + h], aq);
        ak = fmaf(xv, sWk[d * WPITCH + h], ak);
        av = fmaf(xv, sWv[d * WPITCH + h], av);
    }
    int row = row0 + r;
    g_q[row * HEAD + h] = aq;
    g_k[row * HEAD + h] = ak;
    g_v[row * HEAD + h] = av;
}

// ---------------- Kernel 2: flash attention partial (split-K) ----------------
// grid = (T/BR, NSPLIT, BATCH), block = BR threads, one thread per query row.
// Chunked (4-key) online softmax; all inner math in packed f32x2.
__global__ __launch_bounds__(BR) void flash_kernel() {
    __shared__ float Ks[BC * HEAD];
    __shared__ float Vs[BC * HEAD];

    int qtile = blockIdx.x, split = blockIdx.y, b = blockIdx.z;
    int tid = threadIdx.x;
    int q_idx = qtile * BR + tid;

    int kv_begin = split * SPLIT_LEN;
    int kv_end = min((split + 1) * SPLIT_LEN, qtile * BR + BR);  // block-uniform causal clip
    int base = split * BT + (b * T_LEN + q_idx);

    if (kv_begin >= kv_end) {  // block-uniform: split entirely above the diagonal
        g_m[base] = -CUDART_INF_F;
        g_l[base] = 0.f;
        return;                 // g_acc untouched (static zeros), combine weights it by 0
    }

    const float* kb = g_k + b * T_LEN * HEAD;
    const float* vb = g_v + b * T_LEN * HEAD;

    // q row in packed registers
    u64 q2[16];
    {
        const ulonglong2* qg = reinterpret_cast<const ulonglong2*>(g_q + (b * T_LEN + q_idx) * HEAD);
#pragma unroll
        for (int i = 0; i < 8; ++i) { ulonglong2 t = qg[i]; q2[2 * i] = t.x; q2[2 * i + 1] = t.y; }
    }

    float m = -CUDART_INF_F;
    float l = 0.f;
    u64 a2[16];
#pragma unroll
    for (int i = 0; i < 16; ++i) a2[i] = 0ull;

    for (int t0 = kv_begin; t0 < kv_end; t0 += BC) {
        // cooperative full-tile load (tile bounds are always multiples of BC here)
        {
            const float4* kg = reinterpret_cast<const float4*>(kb + t0 * HEAD);
            const float4* vg = reinterpret_cast<const float4*>(vb + t0 * HEAD);
            float4* ks4 = reinterpret_cast<float4*>(Ks);
            float4* vs4 = reinterpret_cast<float4*>(Vs);
#pragma unroll
            for (int i = 0; i < 8; ++i) {
                int idx = i * BR + tid;
                ks4[idx] = kg[idx];
                vs4[idx] = vg[idx];
            }
        }
        __syncthreads();

        int jlim = min(BC, q_idx - t0 + 1);  // per-thread causal bound, >= 1

        for (int jj = 0; jj < jlim; jj += 4) {
            float s[4];
#pragma unroll
            for (int u = 0; u < 4; ++u) {
                const ulonglong2* kj = reinterpret_cast<const ulonglong2*>(Ks + (jj + u) * HEAD);
                u64 d0 = 0ull, d1 = 0ull, d2 = 0ull, d3 = 0ull;
#pragma unroll
                for (int i = 0; i < 4; ++i) {
                    ulonglong2 ka = kj[2 * i];
                    ulonglong2 kc = kj[2 * i + 1];
                    d0 = ffma2(q2[4 * i + 0], ka.x, d0);
                    d1 = ffma2(q2[4 * i + 1], ka.y, d1);
                    d2 = ffma2(q2[4 * i + 2], kc.x, d2);
                    d3 = ffma2(q2[4 * i + 3], kc.y, d3);
                }
                u64 e = fadd2(fadd2(d0, d1), fadd2(d2, d3));
                float lo, hi; unpack2(e, lo, hi);
                float sv = (lo + hi) * SCALE2;
                bool valid = (jj + u < jlim) && (sv != 0.0f);  // faithful: tril==0 also masks exact zeros
                s[u] = valid ? sv : -CUDART_INF_F;
            }

            float smax = fmaxf(fmaxf(s[0], s[1]), fmaxf(s[2], s[3]));
            float m_new = fmaxf(m, smax);
            if (m_new == -CUDART_INF_F) continue;  // whole chunk masked, nothing seen yet

            float c = exp2_approx(m - m_new);       // ==1 when max unchanged; ==0 when m was -inf
            m = m_new;
            float p0 = exp2_approx(s[0] - m);       // ex2(-inf)=0 for masked lanes
            float p1 = exp2_approx(s[1] - m);
            float p2 = exp2_approx(s[2] - m);
            float p3 = exp2_approx(s[3] - m);
            l = l * c + ((p0 + p1) + (p2 + p3));

            u64 cc = pack2(c, c);
#pragma unroll
            for (int i = 0; i < 16; ++i) a2[i] = fmul2(a2[i], cc);

            float p[4] = {p0, p1, p2, p3};
#pragma unroll
            for (int u = 0; u < 4; ++u) {
                u64 pp = pack2(p[u], p[u]);
                const ulonglong2* vj = reinterpret_cast<const ulonglong2*>(Vs + (jj + u) * HEAD);
#pragma unroll
                for (int i = 0; i < 8; ++i) {
                    ulonglong2 vv = vj[i];
                    a2[2 * i]     = ffma2(pp, vv.x, a2[2 * i]);
                    a2[2 * i + 1] = ffma2(pp, vv.y, a2[2 * i + 1]);
                }
            }
        }
        __syncthreads();
    }

    // write partials: layout [split][b*T + q]
    g_m[base] = m;
    g_l[base] = l;
    ulonglong2* ag = reinterpret_cast<ulonglong2*>(g_acc + base * HEAD);
#pragma unroll
    for (int i = 0; i < 8; ++i) {
        ulonglong2 t; t.x = a2[2 * i]; t.y = a2[2 * i + 1];
        ag[i] = t;
    }
}

// ---------------- Kernel 3: split-K combine ----------------
__global__ void combine_kernel(float* __restrict__ out) {
    int bt = blockIdx.x * blockDim.x + threadIdx.x;
    if (bt >= BT) return;

    float ms[NSPLIT], ls[NSPLIT];
    float M = -CUDART_INF_F;
#pragma unroll
    for (int s = 0; s < NSPLIT; ++s) {
        ms[s] = g_m[s * BT + bt];
        ls[s] = g_l[s * BT + bt];
        M = fmaxf(M, ms[s]);
    }
    float w[NSPLIT];
    float L = 0.f;
#pragma unroll
    for (int s = 0; s < NSPLIT; ++s) {
        w[s] = (ms[s] == -CUDART_INF_F) ? 0.f : exp2_approx(ms[s] - M);
        L = fmaf(ls[s], w[s], L);
    }
    float inv = 1.0f / L;

    float4* og = reinterpret_cast<float4*>(out + bt * HEAD);
#pragma unroll
    for (int i = 0; i < 8; ++i) {
        float4 o = make_float4(0.f, 0.f, 0.f, 0.f);
#pragma unroll
        for (int s = 0; s < NSPLIT; ++s) {
            if (w[s] != 0.f) {
                const float4 a = reinterpret_cast<const float4*>(
                    g_acc + (s * BT + bt) * HEAD)[i];
                o.x = fmaf(a.x, w[s], o.x);
                o.y = fmaf(a.y, w[s], o.y);
                o.z = fmaf(a.z, w[s], o.z);
                o.w = fmaf(a.w, w[s], o.w);
            }
        }
        o.x *= inv; o.y *= inv; o.z *= inv; o.w *= inv;
        og[i] = o;
    }
}

extern "C" void kernel_launch(void* const* d_in, const int* in_sizes, int n_in,
                              void* d_out, int out_size) {
    const float* x  = (const float*)d_in[0];
    const float* Wq = (const float*)d_in[1];
    const float* Wk = (const float*)d_in[2];
    const float* Wv = (const float*)d_in[3];
    float* out = (float*)d_out;

    proj_kernel<<<BT / 8, 256>>>(x, Wq, Wk, Wv);
    flash_kernel<<<dim3(T_LEN / BR, NSPLIT, BATCH), BR>>>();
    combine_kernel<<<(BT + 127) / 128, 128>>>(out);
}